// round 1
// baseline (speedup 1.0000x reference)
#include <cuda_runtime.h>
#include <math.h>

#define HIDDEN 2048
#define NH     16
#define HD     128
#define KVC    512
#define QC     1536
#define RD     64
#define BATCH  2
#define SEQ    2048
#define AD     192              // HD + RD
#define MR     (BATCH*SEQ)      // 4096 token rows

// ---------------- scratch (static device globals; no allocs allowed) ----------------
__device__ float g_kvc [MR*KVC];
__device__ float g_qc  [MR*QC];
__device__ float g_kc  [MR*NH*HD];
__device__ float g_v   [MR*NH*HD];
__device__ float g_kr  [MR*NH*RD];
__device__ float g_quc [MR*NH*HD];
__device__ float g_qr  [MR*NH*RD];
__device__ float g_Kp  [(size_t)BATCH*NH*SEQ*AD];   // packed K: [b,h,s,192]
__device__ float g_Qp  [(size_t)BATCH*NH*SEQ*AD];   // packed Q: [b,h,s,192]
__device__ float g_ctx [MR*NH*HD];                  // context in [b,s,h*128] layout
__device__ float g_sinT[SEQ*(RD/2)];
__device__ float g_cosT[SEQ*(RD/2)];

// ---------------- RoPE sin/cos table (double precision to match fp32 ref closely) ----
__global__ void rope_table_kernel() {
    int i = blockIdx.x * blockDim.x + threadIdx.x;
    if (i >= SEQ * (RD/2)) return;
    int s = i >> 5;        // RD/2 = 32
    int p = i & 31;
    double inv = pow(10000.0, -((double)p) / 32.0);
    double a = (double)s * inv;
    g_sinT[i] = (float)sin(a);
    g_cosT[i] = (float)cos(a);
}

// ---------------- generic SGEMM with bias: C[M,N] = A[M,K] @ W[K,N] + bias ----------
// BM=BN=128, BK=8, 256 threads, 8x8 per thread. M,N multiples of 128, K multiple of 8.
__global__ __launch_bounds__(256) void sgemm_bias(
    const float* __restrict__ A, const float* __restrict__ W,
    const float* __restrict__ bias, float* __restrict__ C,
    int M, int N, int K)
{
    __shared__ float As[8][128];   // transposed A tile: As[k][row]
    __shared__ float Bs[8][128];   // Bs[k][col]

    const int t  = threadIdx.x;
    const int tx = t & 15;
    const int ty = t >> 4;
    const int row0 = blockIdx.y * 128;
    const int col0 = blockIdx.x * 128;

    const int arow = t >> 1;          // 0..127
    const int acol = (t & 1) * 4;     // 0 or 4
    const int brow = t >> 5;          // 0..7
    const int bcol = (t & 31) * 4;    // 0..124

    float acc[8][8];
    #pragma unroll
    for (int i = 0; i < 8; i++)
        #pragma unroll
        for (int j = 0; j < 8; j++) acc[i][j] = 0.f;

    for (int k0 = 0; k0 < K; k0 += 8) {
        float4 av = *(const float4*)(A + (size_t)(row0 + arow) * K + k0 + acol);
        float4 bv = *(const float4*)(W + (size_t)(k0 + brow) * N + col0 + bcol);
        __syncthreads();
        As[acol + 0][arow] = av.x;
        As[acol + 1][arow] = av.y;
        As[acol + 2][arow] = av.z;
        As[acol + 3][arow] = av.w;
        *(float4*)&Bs[brow][bcol] = bv;
        __syncthreads();
        #pragma unroll
        for (int kk = 0; kk < 8; kk++) {
            float a[8], b[8];
            #pragma unroll
            for (int i = 0; i < 8; i++) a[i] = As[kk][ty * 8 + i];
            #pragma unroll
            for (int j = 0; j < 8; j++) b[j] = Bs[kk][tx * 8 + j];
            #pragma unroll
            for (int i = 0; i < 8; i++)
                #pragma unroll
                for (int j = 0; j < 8; j++)
                    acc[i][j] = fmaf(a[i], b[j], acc[i][j]);
        }
    }

    #pragma unroll
    for (int i = 0; i < 8; i++) {
        int r = row0 + ty * 8 + i;
        #pragma unroll
        for (int j = 0; j < 8; j += 4) {
            int c = col0 + tx * 8 + j;
            float4 o;
            o.x = acc[i][j+0] + bias[c+0];
            o.y = acc[i][j+1] + bias[c+1];
            o.z = acc[i][j+2] + bias[c+2];
            o.w = acc[i][j+3] + bias[c+3];
            *(float4*)(C + (size_t)r * N + c) = o;
        }
    }
}

// ---------------- pack Q/K: gather content + rope halves into [b,h,s,192] -----------
__global__ void pack_qk(const float* __restrict__ cflat, const float* __restrict__ rflat,
                        float* __restrict__ out)
{
    long long idx = (long long)blockIdx.x * blockDim.x + threadIdx.x;
    const long long total = (long long)BATCH * NH * SEQ * AD;
    if (idx >= total) return;
    int d = (int)(idx % AD);
    int s = (int)((idx / AD) % SEQ);
    int h = (int)((idx / ((long long)AD * SEQ)) % NH);
    int b = (int)(idx / ((long long)AD * SEQ * NH));
    int row = b * SEQ + s;
    float val;
    if (d < HD) {
        val = cflat[(size_t)row * (NH*HD) + h * HD + d];
    } else {
        int j = d - HD;
        int p = j >> 1;
        const float* rp = rflat + (size_t)row * (NH*RD) + h * RD + 2 * p;
        float x0 = rp[0], x1 = rp[1];
        float cc = g_cosT[s * 32 + p];
        float sn = g_sinT[s * 32 + p];
        val = (j & 1) ? (x0 * sn + x1 * cc) : (x0 * cc - x1 * sn);
    }
    out[idx] = val;   // idx == ((b*NH+h)*SEQ+s)*AD + d
}

// ---------------- flash attention (fp32, causal) ------------------------------------
// grid: (SEQ/64 q-tiles, BATCH*NH). 256 threads. BM=BN=64, D_qk=192, D_v=128.
#define QK_STR 193   // odd stride -> at most 2-way LDS conflicts on K reads
#define PS_STR 66

__global__ __launch_bounds__(256) void attn_kernel()
{
    extern __shared__ float sm[];
    float* Qs = sm;                      // [64][QK_STR]
    float* Ks = Qs + 64 * QK_STR;        // [64][QK_STR]
    float* Vs = Ks + 64 * QK_STR;        // [64][128]
    float* Ps = Vs + 64 * 128;           // [64][PS_STR]

    const int t  = threadIdx.x;
    const int tx = t & 15;
    const int ty = t >> 4;
    const int qt = blockIdx.x;
    const int bh = blockIdx.y;
    const int b  = bh >> 4;
    const int h  = bh & 15;
    const int q0 = qt * 64;
    const float scale = rsqrtf((float)AD);

    // load Q tile -> Qs[r][d] (row-major, odd stride; scalar STS, coalesced LDG)
    for (int i = t; i < 64 * 48; i += 256) {
        int r  = i / 48;
        int d4 = (i % 48) * 4;
        float4 v4 = *(const float4*)(g_Qp + ((size_t)bh * SEQ + q0 + r) * AD + d4);
        float* dst = Qs + r * QK_STR + d4;
        dst[0] = v4.x; dst[1] = v4.y; dst[2] = v4.z; dst[3] = v4.w;
    }

    float m_i[4], l_i[4], o[4][8];
    #pragma unroll
    for (int i = 0; i < 4; i++) {
        m_i[i] = -1e30f; l_i[i] = 0.f;
        #pragma unroll
        for (int j = 0; j < 8; j++) o[i][j] = 0.f;
    }

    for (int kt = 0; kt <= qt; kt++) {
        int k0 = kt * 64;
        __syncthreads();  // previous tile's Ks/Vs/Ps reads complete

        // load K tile
        for (int i = t; i < 64 * 48; i += 256) {
            int r  = i / 48;
            int d4 = (i % 48) * 4;
            float4 v4 = *(const float4*)(g_Kp + ((size_t)bh * SEQ + k0 + r) * AD + d4);
            float* dst = Ks + r * QK_STR + d4;
            dst[0] = v4.x; dst[1] = v4.y; dst[2] = v4.z; dst[3] = v4.w;
        }
        // load V tile (directly from flat [b,s,h*128] layout)
        for (int i = t; i < 64 * 32; i += 256) {
            int r  = i / 32;
            int c4 = (i % 32) * 4;
            float4 v4 = *(const float4*)(g_v + ((size_t)b * SEQ + k0 + r) * (NH*HD) + h * HD + c4);
            *(float4*)&Vs[r * 128 + c4] = v4;
        }
        __syncthreads();

        // scores: acc[i][j] = Q[ty*4+i] . K[tx*4+j]
        float acc[4][4];
        #pragma unroll
        for (int i = 0; i < 4; i++)
            #pragma unroll
            for (int j = 0; j < 4; j++) acc[i][j] = 0.f;

        #pragma unroll 2
        for (int d = 0; d < AD; d++) {
            float qf[4], kf[4];
            #pragma unroll
            for (int i = 0; i < 4; i++) qf[i] = Qs[(ty * 4 + i) * QK_STR + d];
            #pragma unroll
            for (int j = 0; j < 4; j++) kf[j] = Ks[(tx * 4 + j) * QK_STR + d];
            #pragma unroll
            for (int i = 0; i < 4; i++)
                #pragma unroll
                for (int j = 0; j < 4; j++)
                    acc[i][j] = fmaf(qf[i], kf[j], acc[i][j]);
        }

        // scale + causal mask (only diagonal tile needs it)
        #pragma unroll
        for (int i = 0; i < 4; i++)
            #pragma unroll
            for (int j = 0; j < 4; j++) {
                acc[i][j] *= scale;
                if (kt == qt && (k0 + tx * 4 + j) > (q0 + ty * 4 + i))
                    acc[i][j] = -1e9f;
            }

        // online softmax: reduce over 16 lanes sharing a row group
        float mt[4];
        #pragma unroll
        for (int i = 0; i < 4; i++)
            mt[i] = fmaxf(fmaxf(acc[i][0], acc[i][1]), fmaxf(acc[i][2], acc[i][3]));
        #pragma unroll
        for (int off = 1; off < 16; off <<= 1)
            #pragma unroll
            for (int i = 0; i < 4; i++)
                mt[i] = fmaxf(mt[i], __shfl_xor_sync(0xffffffffu, mt[i], off));

        float alpha[4];
        #pragma unroll
        for (int i = 0; i < 4; i++) {
            float mn = fmaxf(m_i[i], mt[i]);
            alpha[i] = __expf(m_i[i] - mn);
            m_i[i] = mn;
        }

        float rs[4];
        #pragma unroll
        for (int i = 0; i < 4; i++) {
            rs[i] = 0.f;
            #pragma unroll
            for (int j = 0; j < 4; j++) {
                acc[i][j] = __expf(acc[i][j] - m_i[i]);
                rs[i] += acc[i][j];
            }
        }
        #pragma unroll
        for (int off = 1; off < 16; off <<= 1)
            #pragma unroll
            for (int i = 0; i < 4; i++)
                rs[i] += __shfl_xor_sync(0xffffffffu, rs[i], off);

        #pragma unroll
        for (int i = 0; i < 4; i++) {
            l_i[i] = l_i[i] * alpha[i] + rs[i];
            #pragma unroll
            for (int j = 0; j < 8; j++) o[i][j] *= alpha[i];
        }

        // stage P to shared for the PV GEMM
        #pragma unroll
        for (int i = 0; i < 4; i++)
            #pragma unroll
            for (int j = 0; j < 4; j++)
                Ps[(ty * 4 + i) * PS_STR + tx * 4 + j] = acc[i][j];
        __syncthreads();

        // O[i][c] += P[i][k] * V[k][c], c = tx*8 + j
        #pragma unroll 2
        for (int k = 0; k < 64; k++) {
            float pf[4];
            #pragma unroll
            for (int i = 0; i < 4; i++) pf[i] = Ps[(ty * 4 + i) * PS_STR + k];
            float4 v0 = *(float4*)&Vs[k * 128 + tx * 8];
            float4 v1 = *(float4*)&Vs[k * 128 + tx * 8 + 4];
            #pragma unroll
            for (int i = 0; i < 4; i++) {
                o[i][0] = fmaf(pf[i], v0.x, o[i][0]);
                o[i][1] = fmaf(pf[i], v0.y, o[i][1]);
                o[i][2] = fmaf(pf[i], v0.z, o[i][2]);
                o[i][3] = fmaf(pf[i], v0.w, o[i][3]);
                o[i][4] = fmaf(pf[i], v1.x, o[i][4]);
                o[i][5] = fmaf(pf[i], v1.y, o[i][5]);
                o[i][6] = fmaf(pf[i], v1.z, o[i][6]);
                o[i][7] = fmaf(pf[i], v1.w, o[i][7]);
            }
        }
    }

    // epilogue: normalize + scatter to [b,s,h*128]
    #pragma unroll
    for (int i = 0; i < 4; i++) {
        float inv = 1.f / l_i[i];
        int r = q0 + ty * 4 + i;
        float4 w0, w1;
        w0.x = o[i][0]*inv; w0.y = o[i][1]*inv; w0.z = o[i][2]*inv; w0.w = o[i][3]*inv;
        w1.x = o[i][4]*inv; w1.y = o[i][5]*inv; w1.z = o[i][6]*inv; w1.w = o[i][7]*inv;
        float* dst = g_ctx + ((size_t)b * SEQ + r) * (NH*HD) + h * HD + tx * 8;
        *(float4*)(dst)     = w0;
        *(float4*)(dst + 4) = w1;
    }
}

// ---------------- host launch ---------------------------------------------------------
extern "C" void kernel_launch(void* const* d_in, const int* in_sizes, int n_in,
                              void* d_out, int out_size)
{
    const float* x        = (const float*)d_in[0];
    // d_in[1] = attention_mask (all valid in this problem; causal mask only)
    const float* kv_down_w   = (const float*)d_in[2];
    const float* kv_down_b   = (const float*)d_in[3];
    const float* key_up_w    = (const float*)d_in[4];
    const float* key_up_b    = (const float*)d_in[5];
    const float* value_up_w  = (const float*)d_in[6];
    const float* value_up_b  = (const float*)d_in[7];
    const float* key_rope_w  = (const float*)d_in[8];
    const float* key_rope_b  = (const float*)d_in[9];
    const float* query_down_w= (const float*)d_in[10];
    const float* query_down_b= (const float*)d_in[11];
    const float* query_up_w  = (const float*)d_in[12];
    const float* query_up_b  = (const float*)d_in[13];
    const float* query_rope_w= (const float*)d_in[14];
    const float* query_rope_b= (const float*)d_in[15];
    const float* out_w       = (const float*)d_in[16];
    const float* out_b       = (const float*)d_in[17];
    float* out = (float*)d_out;

    float *p_kvc, *p_qc, *p_kc, *p_v, *p_kr, *p_quc, *p_qr, *p_Kp, *p_Qp, *p_ctx;
    cudaGetSymbolAddress((void**)&p_kvc, g_kvc);
    cudaGetSymbolAddress((void**)&p_qc,  g_qc);
    cudaGetSymbolAddress((void**)&p_kc,  g_kc);
    cudaGetSymbolAddress((void**)&p_v,   g_v);
    cudaGetSymbolAddress((void**)&p_kr,  g_kr);
    cudaGetSymbolAddress((void**)&p_quc, g_quc);
    cudaGetSymbolAddress((void**)&p_qr,  g_qr);
    cudaGetSymbolAddress((void**)&p_Kp,  g_Kp);
    cudaGetSymbolAddress((void**)&p_Qp,  g_Qp);
    cudaGetSymbolAddress((void**)&p_ctx, g_ctx);

    // RoPE table
    rope_table_kernel<<<(SEQ*32 + 255)/256, 256>>>();

    // projections
    sgemm_bias<<<dim3(KVC/128,   MR/128), 256>>>(x,     kv_down_w,    kv_down_b,    p_kvc, MR, KVC,    HIDDEN);
    sgemm_bias<<<dim3(QC/128,    MR/128), 256>>>(x,     query_down_w, query_down_b, p_qc,  MR, QC,     HIDDEN);
    sgemm_bias<<<dim3((NH*HD)/128, MR/128), 256>>>(p_kvc, key_up_w,   key_up_b,     p_kc,  MR, NH*HD,  KVC);
    sgemm_bias<<<dim3((NH*HD)/128, MR/128), 256>>>(p_kvc, value_up_w, value_up_b,   p_v,   MR, NH*HD,  KVC);
    sgemm_bias<<<dim3((NH*RD)/128, MR/128), 256>>>(p_kvc, key_rope_w, key_rope_b,   p_kr,  MR, NH*RD,  KVC);
    sgemm_bias<<<dim3((NH*HD)/128, MR/128), 256>>>(p_qc,  query_up_w, query_up_b,   p_quc, MR, NH*HD,  QC);
    sgemm_bias<<<dim3((NH*RD)/128, MR/128), 256>>>(p_qc,  query_rope_w, query_rope_b, p_qr, MR, NH*RD, QC);

    // pack Q/K with rope
    {
        long long total = (long long)BATCH * NH * SEQ * AD;
        int blocks = (int)((total + 255) / 256);
        pack_qk<<<blocks, 256>>>(p_kc,  p_kr, p_Kp);
        pack_qk<<<blocks, 256>>>(p_quc, p_qr, p_Qp);
    }

    // attention
    {
        size_t smem = (size_t)(64*QK_STR*2 + 64*128 + 64*PS_STR) * sizeof(float);
        cudaFuncSetAttribute(attn_kernel, cudaFuncAttributeMaxDynamicSharedMemorySize, (int)smem);
        attn_kernel<<<dim3(SEQ/64, BATCH*NH), 256, smem>>>();
    }

    // output projection -> d_out
    sgemm_bias<<<dim3(HIDDEN/128, MR/128), 256>>>(p_ctx, out_w, out_b, out, MR, HIDDEN, NH*HD);
}